// round 11
// baseline (speedup 1.0000x reference)
#include <cuda_runtime.h>
#include <cuda_fp16.h>
#include <math.h>
#include <stdint.h>

#define G 4
#define NNODE 1024
#define FDIM 256
#define HDIM 256
#define BATCH 32
#define LAYERS 4
#define NCTA 128
#define NTHR 512
#define CTAS_PER_G 32

// ---------------- scratch (device globals; no allocation allowed) -----------
__device__ __half g_ah [G * NNODE * NNODE];          // adjacency, half, x1024
__device__ __half g_xin[G * NNODE * FDIM];           // input feats, half
__device__ __half g_wh [(1 + LAYERS) * HDIM * HDIM]; // weights, half
__device__ __half g_h0h[G * NNODE * HDIM];           // h0 half (residual + layer0 in)
__device__ __half g_xa [G * NNODE * HDIM];           // ping
__device__ __half g_xb [G * NNODE * HDIM];           // pong
__device__ float  g_xl [G * NNODE * HDIM];           // final output fp32
__device__ float  g_part[BATCH * 8 * HDIM];          // reduce partials
__device__ float  g_cnt [BATCH * 8];                 // reduce counts
__device__ unsigned g_bar_epoch;                     // grid barrier epoch
__device__ unsigned g_bar_count;                     // grid barrier counter

struct alignas(256) GraphBar {
    unsigned count; unsigned pad1[31];
    unsigned epoch; unsigned pad2[31];
};
__device__ GraphBar g_gb[G];

// ---------------- tiling ----------------------------------------------------
// CTA tile: 32 rows x 256 cols. 128 CTAs (1/SM). Warps: 2(M) x 8(N), 16x32 each.
#define BK 64
#define ASTR_B 144                         // A chunk row stride bytes (72 halves)
#define BSTR_B 528                         // B/W chunk row stride bytes (264 halves)
#define A_STG_B (32 * ASTR_B)              // 4608
#define B_STG_B (64 * BSTR_B)              // 33792
#define OFF_BIAS 0
#define OFF_T 1024
#define OFF_A (OFF_T + 32 * BSTR_B)        // t tile: 32 x 528B = 16896 -> 17920
#define OFF_B (OFF_A + 3 * A_STG_B)        // 17920 + 13824 = 31744
#define SMEM_BYTES (OFF_B + 3 * B_STG_B)   // 31744 + 101376 = 133120

__device__ __forceinline__ uint32_t smem_u32(const void* p) {
    uint32_t a;
    asm("{ .reg .u64 t; cvta.to.shared.u64 t, %1; cvt.u32.u64 %0, t; }" : "=r"(a) : "l"(p));
    return a;
}
__device__ __forceinline__ void cpa16(uint32_t dst, const void* src) {
    asm volatile("cp.async.cg.shared.global [%0], [%1], 16;" :: "r"(dst), "l"(src));
}
#define CP_COMMIT() asm volatile("cp.async.commit_group;" ::: "memory")
#define CP_WAIT1()  asm volatile("cp.async.wait_group 1;" ::: "memory")
#define CP_WAIT0()  asm volatile("cp.async.wait_group 0;" ::: "memory")

__device__ __forceinline__ void ldsm_x4(uint32_t* r, uint32_t addr) {
    asm volatile("ldmatrix.sync.aligned.m8n8.x4.shared.b16 {%0,%1,%2,%3}, [%4];"
        : "=r"(r[0]), "=r"(r[1]), "=r"(r[2]), "=r"(r[3]) : "r"(addr));
}
__device__ __forceinline__ void ldsm_x4_t(uint32_t* r, uint32_t addr) {
    asm volatile("ldmatrix.sync.aligned.m8n8.x4.trans.shared.b16 {%0,%1,%2,%3}, [%4];"
        : "=r"(r[0]), "=r"(r[1]), "=r"(r[2]), "=r"(r[3]) : "r"(addr));
}
__device__ __forceinline__ void mma_f16(float* d, const uint32_t* a, uint32_t b0, uint32_t b1) {
    asm volatile(
        "mma.sync.aligned.m16n8k16.row.col.f32.f16.f16.f32 "
        "{%0,%1,%2,%3}, {%4,%5,%6,%7}, {%8,%9}, {%0,%1,%2,%3};"
        : "+f"(d[0]), "+f"(d[1]), "+f"(d[2]), "+f"(d[3])
        : "r"(a[0]), "r"(a[1]), "r"(a[2]), "r"(a[3]), "r"(b0), "r"(b1));
}

// ---------------- barriers ---------------------------------------------------
__device__ __forceinline__ void grid_barrier(unsigned target) {
    __syncthreads();
    if (threadIdx.x == 0) {
        __threadfence();
        unsigned old = atomicAdd(&g_bar_count, 1u);
        if (old == NCTA - 1) {
            atomicExch(&g_bar_count, 0u);
            __threadfence();
            atomicAdd(&g_bar_epoch, 1u);
        } else {
            unsigned e;
            do {
                asm volatile("ld.acquire.gpu.u32 %0, [%1];" : "=r"(e) : "l"(&g_bar_epoch));
                if ((int)(e - target) >= 0) break;
                __nanosleep(32);
            } while (true);
        }
    }
    __syncthreads();
}
__device__ __forceinline__ void graph_barrier(GraphBar* b, unsigned target) {
    __syncthreads();
    if (threadIdx.x == 0) {
        __threadfence();
        unsigned old = atomicAdd(&b->count, 1u);
        if (old == CTAS_PER_G - 1) {
            atomicExch(&b->count, 0u);
            __threadfence();
            atomicAdd(&b->epoch, 1u);
        } else {
            unsigned e;
            do {
                asm volatile("ld.acquire.gpu.u32 %0, [%1];" : "=r"(e) : "l"(&b->epoch));
                if ((int)(e - target) >= 0) break;
                __nanosleep(32);
            } while (true);
        }
    }
    __syncthreads();
}

// ---------------- dense from t-smem ------------------------------------------
// out = act(t(32x256,smem) @ W(256x256,gmem) + bias). ACT 1 relu, 2 tanh.
template <int ACT, int OUTF32>
__device__ void dense_from_t(char* smraw, const __half* W, const float* bias,
                             __half* Ch, float* Cf, int cta) {
    const int tid = threadIdx.x, wid = tid >> 5, lane = tid & 31;
    const int wm = wid >> 3, wn = wid & 7, gid = lane >> 2, tig = lane & 3;
    const int l15 = lane & 15, l4 = lane >> 4;
    float* sbias = (float*)(smraw + OFF_BIAS);
    const uint32_t uT = smem_u32(smraw + OFF_T);
    const uint32_t uB = smem_u32(smraw + OFF_B);
    if (tid < HDIM) sbias[tid] = bias[tid];

    auto loadW = [&](int c, int s) {
        const __half* Wg = W + (long)(c * BK) * HDIM;
        uint32_t bBase = uB + s * B_STG_B;
        #pragma unroll
        for (int i = 0; i < 4; i++) {
            int idx = tid + i * NTHR;
            int r = idx >> 5, q = idx & 31;
            cpa16(bBase + r * BSTR_B + q * 16, Wg + (long)r * HDIM + q * 8);
        }
    };
    const uint32_t aLane = (uint32_t)((wm * 16 + l15) * BSTR_B + l4 * 16);
    const uint32_t bLane = (uint32_t)(l15 * BSTR_B + (wn * 32 + l4 * 8) * 2);

    float e[4][4] = {};
    loadW(0, 0); CP_COMMIT();
    loadW(1, 1); CP_COMMIT();
    for (int c = 0; c < 4; c++) {
        CP_WAIT1();
        __syncthreads();
        if (c + 2 < 4) loadW(c + 2, (c + 2) % 3);
        CP_COMMIT();
        const uint32_t aS = uT + aLane + c * 128;
        const uint32_t bS = uB + (c % 3) * B_STG_B + bLane;
        uint32_t af[2][4], b0f[2][4], b1f[2][4];
        ldsm_x4(af[0], aS);
        ldsm_x4_t(b0f[0], bS);
        ldsm_x4_t(b1f[0], bS + 32);
        #pragma unroll
        for (int ks = 0; ks < 4; ks++) {
            const int cu = ks & 1, nx = cu ^ 1;
            if (ks < 3) {
                ldsm_x4(af[nx], aS + (ks + 1) * 32);
                ldsm_x4_t(b0f[nx], bS + (ks + 1) * 16 * BSTR_B);
                ldsm_x4_t(b1f[nx], bS + (ks + 1) * 16 * BSTR_B + 32);
            }
            mma_f16(e[0], af[cu], b0f[cu][0], b0f[cu][1]);
            mma_f16(e[1], af[cu], b0f[cu][2], b0f[cu][3]);
            mma_f16(e[2], af[cu], b1f[cu][0], b1f[cu][1]);
            mma_f16(e[3], af[cu], b1f[cu][2], b1f[cu][3]);
        }
    }
    CP_WAIT0();

    #pragma unroll
    for (int nt = 0; nt < 4; nt++) {
        #pragma unroll
        for (int hf = 0; hf < 2; hf++) {
            const long row = (long)cta * 32 + wm * 16 + hf * 8 + gid;
            const int col = wn * 32 + nt * 8 + 2 * tig;
            float v0 = e[nt][hf * 2 + 0] + sbias[col];
            float v1 = e[nt][hf * 2 + 1] + sbias[col + 1];
            if (ACT == 1) { v0 = fmaxf(v0, 0.0f); v1 = fmaxf(v1, 0.0f); }
            if (ACT == 2) { v0 = tanhf(v0); v1 = tanhf(v1); }
            if (OUTF32)
                *(float2*)(Cf + row * HDIM + col) = make_float2(v0, v1);
            else
                *(__half2*)(Ch + row * HDIM + col) = __floats2half2_rn(v0, v1);
        }
    }
}

// ---------------- A@x into t-smem --------------------------------------------
// t(32x256, smem half) = inv1024 * (A[g, rows, :] @ x[g])   K = 1024, 16 chunks
__device__ void ax_to_t(char* smraw, const __half* Abase, const __half* X) {
    const int tid = threadIdx.x, wid = tid >> 5, lane = tid & 31;
    const int wm = wid >> 3, wn = wid & 7, gid = lane >> 2, tig = lane & 3;
    const int l15 = lane & 15, l4 = lane >> 4;
    const uint32_t uT = smem_u32(smraw + OFF_T);
    const uint32_t uA = smem_u32(smraw + OFF_A);
    const uint32_t uB = smem_u32(smraw + OFF_B);

    auto load_stage = [&](int c, int s) {
        uint32_t aBase = uA + s * A_STG_B;
        uint32_t bBase = uB + s * B_STG_B;
        if (tid < 256) {                       // A: 32 rows x 8 x 16B
            int r = tid >> 3, q = tid & 7;
            cpa16(aBase + r * ASTR_B + q * 16,
                  Abase + (long)r * NNODE + c * BK + q * 8);
        }
        #pragma unroll
        for (int i = 0; i < 4; i++) {          // B: 64 rows x 32 x 16B
            int idx = tid + i * NTHR;
            int r = idx >> 5, q = idx & 31;
            cpa16(bBase + r * BSTR_B + q * 16,
                  X + (long)(c * BK + r) * HDIM + q * 8);
        }
    };
    const uint32_t aLane = (uint32_t)((wm * 16 + l15) * ASTR_B + l4 * 16);
    const uint32_t bLane = (uint32_t)(l15 * BSTR_B + (wn * 32 + l4 * 8) * 2);

    float d[4][4] = {};
    load_stage(0, 0); CP_COMMIT();
    load_stage(1, 1); CP_COMMIT();
    const int NC = NNODE / BK;                 // 16
    for (int c = 0; c < NC; c++) {
        CP_WAIT1();
        __syncthreads();
        if (c + 2 < NC) load_stage(c + 2, (c + 2) % 3);
        CP_COMMIT();
        const uint32_t aS = uA + (c % 3) * A_STG_B + aLane;
        const uint32_t bS = uB + (c % 3) * B_STG_B + bLane;
        uint32_t af[2][4], b0f[2][4], b1f[2][4];
        ldsm_x4(af[0], aS);
        ldsm_x4_t(b0f[0], bS);
        ldsm_x4_t(b1f[0], bS + 32);
        #pragma unroll
        for (int ks = 0; ks < 4; ks++) {
            const int cu = ks & 1, nx = cu ^ 1;
            if (ks < 3) {
                ldsm_x4(af[nx], aS + (ks + 1) * 32);
                ldsm_x4_t(b0f[nx], bS + (ks + 1) * 16 * BSTR_B);
                ldsm_x4_t(b1f[nx], bS + (ks + 1) * 16 * BSTR_B + 32);
            }
            mma_f16(d[0], af[cu], b0f[cu][0], b0f[cu][1]);
            mma_f16(d[1], af[cu], b0f[cu][2], b0f[cu][3]);
            mma_f16(d[2], af[cu], b1f[cu][0], b1f[cu][1]);
            mma_f16(d[3], af[cu], b1f[cu][2], b1f[cu][3]);
        }
    }
    CP_WAIT0();

    // store t to smem (half, scaled)
    const float inv = 1.0f / 1024.0f;
    char* tS = smraw + OFF_T;
    #pragma unroll
    for (int nt = 0; nt < 4; nt++) {
        #pragma unroll
        for (int hf = 0; hf < 2; hf++) {
            const int row = wm * 16 + hf * 8 + gid;
            const int col = wn * 32 + nt * 8 + 2 * tig;
            *(__half2*)(tS + row * BSTR_B + col * 2) =
                __floats2half2_rn(d[nt][hf * 2] * inv, d[nt][hf * 2 + 1] * inv);
        }
    }
    __syncthreads();
}

// ---------------- the megakernel --------------------------------------------
#define TOT4_A (G * NNODE * NNODE / 4)
#define TOT4_X (G * NNODE * FDIM / 4)
#define TOT4_W ((1 + LAYERS) * HDIM * HDIM / 4)
#define TOT4_WIN (FDIM * HDIM / 4)
#define A_SLICE (TOT4_A / NCTA)               // 8192 float4 per CTA

__global__ void __launch_bounds__(NTHR, 1)
meganet(const float* batch_xs, const float* batch_as,
        const float* w_in, const float* b_in,
        const float* gcn_w, const float* gcn_b,
        const int* gidx, const int* mask, float* out) {
    extern __shared__ char smraw[];
    const int cta = blockIdx.x;
    const int tid = threadIdx.x;
    const int g = cta >> 5;                   // graph of this CTA
    unsigned bt = g_bar_epoch;                // snapshots before any barrier
    unsigned gbt = g_gb[g].epoch;

    // ---- phase P: convert X + W ----
    {
        const float4* x4 = (const float4*)batch_xs;
        const float4* wi = (const float4*)w_in;
        const float4* gw = (const float4*)gcn_w;
        __half2* xh2 = (__half2*)g_xin;
        __half2* wh2 = (__half2*)g_wh;
        const int total = TOT4_X + TOT4_W;
        for (int i = cta * NTHR + tid; i < total; i += NCTA * NTHR) {
            float4 v; __half2* dst;
            if (i < TOT4_X) { v = x4[i]; dst = xh2 + 2 * i; }
            else {
                int j = i - TOT4_X;
                if (j < TOT4_WIN) { v = wi[j]; dst = wh2 + 2 * j; }
                else { v = gw[j - TOT4_WIN]; dst = wh2 + 2 * j; }
            }
            dst[0] = __floats2half2_rn(v.x, v.y);
            dst[1] = __floats2half2_rn(v.z, v.w);
        }
    }
    grid_barrier(++bt);

    // ---- phase 0: h0 = relu(X @ w_in + b); X tile straight into t-smem ----
    {
        const uint32_t uT = smem_u32(smraw + OFF_T);
        #pragma unroll
        for (int i = 0; i < 2; i++) {
            int idx = tid + i * NTHR;
            int r = idx >> 5, q = idx & 31;
            cpa16(uT + r * BSTR_B + q * 16,
                  g_xin + ((long)cta * 32 + r) * FDIM + q * 8);
        }
        CP_COMMIT(); CP_WAIT0();
        __syncthreads();
        dense_from_t<1, 0>(smraw, g_wh, b_in, g_h0h, nullptr, cta);
    }
    // convert this CTA's A slice (overlaps other CTAs' h0 work)
    {
        const float4* a4 = (const float4*)batch_as + (long)cta * A_SLICE;
        __half2* ah2 = (__half2*)g_ah + (long)cta * A_SLICE * 2;
        #pragma unroll 4
        for (int i = tid; i < A_SLICE; i += NTHR) {
            float4 v = a4[i];
            ah2[2 * i + 0] = __floats2half2_rn(v.x * 1024.0f, v.y * 1024.0f);
            ah2[2 * i + 1] = __floats2half2_rn(v.z * 1024.0f, v.w * 1024.0f);
        }
    }
    grid_barrier(++bt);

    // ---- fused GCN layers ----
    const __half* Abase = g_ah + (long)g * NNODE * NNODE
                        + (long)(cta & 31) * 32 * NNODE;
    const __half* cur = g_h0h + (long)g * NNODE * HDIM;
    for (int i = 0; i < LAYERS; i++) {
        ax_to_t(smraw, Abase, cur);
        if (i < LAYERS - 1) {
            __half* nxt = ((i & 1) ? g_xb : g_xa);
            dense_from_t<1, 0>(smraw, g_wh + (size_t)(1 + i) * HDIM * HDIM,
                               gcn_b + i * HDIM, nxt, nullptr, cta);
            cur = nxt + (long)g * NNODE * HDIM;
            graph_barrier(&g_gb[g], ++gbt);
        } else {
            dense_from_t<2, 1>(smraw, g_wh + (size_t)LAYERS * HDIM * HDIM,
                               gcn_b + (LAYERS - 1) * HDIM, nullptr, g_xl, cta);
        }
    }
    grid_barrier(++bt);

    // ---- phase R1: partial masked sums ----
    {
        const int b = cta >> 2;
        const int s = ((cta & 3) << 1) + (tid >> 8);
        const int h = tid & 255;
        const int gg = gidx[b];
        const float* xb = g_xl  + (size_t)gg * NNODE * HDIM;
        const __half* rb = g_h0h + (size_t)gg * NNODE * HDIM;
        const int* mb = mask + b * NNODE;
        float acc = 0.0f, cnt = 0.0f;
        #pragma unroll 4
        for (int n = s * 128; n < s * 128 + 128; n++) {
            float m = (mb[n] != 0) ? 1.0f : 0.0f;
            cnt += m;
            acc += m * (xb[(size_t)n * HDIM + h] +
                        __half2float(rb[(size_t)n * HDIM + h]));
        }
        g_part[(b * 8 + s) * HDIM + h] = acc;
        if (h == 0) g_cnt[b * 8 + s] = cnt;
    }
    grid_barrier(++bt);

    // ---- phase R2: combine (32 CTAs, first 256 threads) ----
    if (cta < BATCH && tid < HDIM) {
        const int b = cta, h = tid;
        float acc = 0.0f, cnt = 0.0f;
        #pragma unroll
        for (int s = 0; s < 8; s++) {
            acc += g_part[(b * 8 + s) * HDIM + h];
            cnt += g_cnt[b * 8 + s];
        }
        out[b * HDIM + h] = acc / fmaxf(cnt, 1.0f);
    }
}

// ---------------- launch -----------------------------------------------------
extern "C" void kernel_launch(void* const* d_in, const int* in_sizes, int n_in,
                              void* d_out, int out_size) {
    const float* batch_xs = (const float*)d_in[0];
    const float* batch_as = (const float*)d_in[1];
    const float* w_in     = (const float*)d_in[2];
    const float* b_in     = (const float*)d_in[3];
    const float* gcn_w    = (const float*)d_in[4];
    const float* gcn_b    = (const float*)d_in[5];
    const int*   gidx     = (const int*)d_in[6];
    const int*   cp_mask  = (const int*)d_in[7];
    float* out = (float*)d_out;

    cudaFuncSetAttribute(meganet, cudaFuncAttributeMaxDynamicSharedMemorySize,
                         SMEM_BYTES);

    meganet<<<NCTA, NTHR, SMEM_BYTES>>>(batch_xs, batch_as, w_in, b_in,
                                        gcn_w, gcn_b, gidx, cp_mask, out);
}